// round 1
// baseline (speedup 1.0000x reference)
#include <cuda_runtime.h>
#include <cuda_bf16.h>
#include <cstdint>

#define NFEAT 256
#define NDIM  128
#define TILE_ROWS 64
#define WPAD 132   // padded row stride (floats) for W1s: keeps float4 reads conflict-free

// Shared mem: W1 transposed [NFEAT][WPAD] + x0 tile [TILE_ROWS][NFEAT]
#define GEMM_SMEM_BYTES ((NFEAT * WPAD + TILE_ROWS * NFEAT) * (int)sizeof(float))

// ---------------------------------------------------------------------------
// GEMM: x1[r, j] = sum_k x0[r, k] * W1[j, k]
// Block: 256 threads, 64 rows x 128 cols per block.
// Thread (warp w, lane l) computes rows [8w..8w+8) x cols [4l..4l+4).
// x0s reads are warp-broadcast (all lanes same address); W1s reads are float4,
// 128 consecutive floats across the warp -> conflict-free.
// ---------------------------------------------------------------------------
__global__ void __launch_bounds__(256, 1)
gemm_kernel(const float* __restrict__ emb_node,
            const float* __restrict__ emb_attri,
            int n_node, int n_total,
            const float* __restrict__ W1,
            float* __restrict__ x1)
{
    extern __shared__ float sm[];
    float* W1s = sm;                      // [NFEAT][WPAD], W1s[k*WPAD + j] = W1[j][k]
    float* x0s = sm + NFEAT * WPAD;       // [TILE_ROWS][NFEAT]

    const int tid = threadIdx.x;

    // Load W1 transposed into shared (coalesced global reads).
    for (int idx = tid; idx < NDIM * NFEAT; idx += 256) {
        int j = idx >> 8;        // row of W1 (output col)
        int k = idx & (NFEAT - 1);
        W1s[k * WPAD + j] = W1[idx];
    }

    const int row0 = blockIdx.x * TILE_ROWS;

    // Load x0 tile (float4, coalesced). Rows beyond n_total -> zeros.
    for (int idx = tid; idx < (TILE_ROWS * NFEAT) / 4; idx += 256) {
        int r  = idx / (NFEAT / 4);
        int kk = idx % (NFEAT / 4);
        int grow = row0 + r;
        float4 v = make_float4(0.f, 0.f, 0.f, 0.f);
        if (grow < n_total) {
            const float* src = (grow < n_node)
                ? (emb_node  + (size_t)grow * NFEAT)
                : (emb_attri + (size_t)(grow - n_node) * NFEAT);
            v = ((const float4*)src)[kk];
        }
        ((float4*)(x0s + r * NFEAT))[kk] = v;
    }
    __syncthreads();

    const int lane = tid & 31;
    const int wrp  = tid >> 5;       // 0..7
    const int c0   = lane * 4;       // output col base
    const int r0   = wrp * 8;        // tile-row base

    float acc[8][4];
    #pragma unroll
    for (int r = 0; r < 8; r++)
        #pragma unroll
        for (int c = 0; c < 4; c++) acc[r][c] = 0.f;

    #pragma unroll 4
    for (int k = 0; k < NFEAT; k++) {
        float4 w = *((const float4*)(W1s + k * WPAD + c0));
        #pragma unroll
        for (int r = 0; r < 8; r++) {
            float a = x0s[(r0 + r) * NFEAT + k];   // warp broadcast
            acc[r][0] += a * w.x;
            acc[r][1] += a * w.y;
            acc[r][2] += a * w.z;
            acc[r][3] += a * w.w;
        }
    }

    #pragma unroll
    for (int r = 0; r < 8; r++) {
        int grow = row0 + r0 + r;
        if (grow < n_total) {
            *((float4*)(x1 + (size_t)grow * NDIM + c0)) =
                make_float4(acc[r][0], acc[r][1], acc[r][2], acc[r][3]);
        }
    }
}

// ---------------------------------------------------------------------------
// SpMM scatter: out[row[e], :] += val[e] * x1[col[e], :]
// One warp handles EDGES_PER_WARP edges; each lane owns 4 consecutive floats
// (float4 gather + red.global.add.v4.f32 scatter). x1 (52 MB) is expected to
// be L2-resident, so gathers hit L2.
// ---------------------------------------------------------------------------
#define EDGES_PER_WARP 4

__global__ void __launch_bounds__(256)
spmm_kernel(const int*   __restrict__ rows,
            const int*   __restrict__ cols,
            const float* __restrict__ vals,
            const float* __restrict__ x1,
            float*       __restrict__ out,
            int nedges)
{
    const int lane = threadIdx.x & 31;
    const int warp = blockIdx.x * (blockDim.x >> 5) + (threadIdx.x >> 5);
    const int e0 = warp * EDGES_PER_WARP;

    int   r[EDGES_PER_WARP];
    int   c[EDGES_PER_WARP];
    float v[EDGES_PER_WARP];

    #pragma unroll
    for (int i = 0; i < EDGES_PER_WARP; i++) {
        int e = e0 + i;
        if (e < nedges) { r[i] = rows[e]; c[i] = cols[e]; v[i] = vals[e]; }
        else            { r[i] = -1; c[i] = 0; v[i] = 0.f; }
    }

    float4 x[EDGES_PER_WARP];
    #pragma unroll
    for (int i = 0; i < EDGES_PER_WARP; i++) {
        if (r[i] >= 0)
            x[i] = ((const float4*)(x1 + (size_t)c[i] * NDIM))[lane];
    }

    #pragma unroll
    for (int i = 0; i < EDGES_PER_WARP; i++) {
        if (r[i] >= 0) {
            float* dst = out + (size_t)r[i] * NDIM + lane * 4;
            float a = x[i].x * v[i];
            float b = x[i].y * v[i];
            float cc = x[i].z * v[i];
            float d = x[i].w * v[i];
            asm volatile("red.global.add.v4.f32 [%0], {%1, %2, %3, %4};"
                         :: "l"(dst), "f"(a), "f"(b), "f"(cc), "f"(d)
                         : "memory");
        }
    }
}

// ---------------------------------------------------------------------------
// kernel_launch
// Inputs (metadata order):
//   0 emb_node  [N_NODE, 256] f32
//   1 emb_attri [N_ATTRI, 256] f32
//   2 W1        [128, 256] f32
//   3 adj_row   [E] i32    4 adj_col [E] i32    5 adj_val [E] f32
//   6 adj2_row  [E] i32    7 adj2_col[E] i32    8 adj2_val[E] f32
// Output: concat(x1, x2, x3), each [N, 128] f32.
// ---------------------------------------------------------------------------
extern "C" void kernel_launch(void* const* d_in, const int* in_sizes, int n_in,
                              void* d_out, int out_size)
{
    const float* emb_node  = (const float*)d_in[0];
    const float* emb_attri = (const float*)d_in[1];
    const float* W1        = (const float*)d_in[2];
    const int*   a_row     = (const int*)d_in[3];
    const int*   a_col     = (const int*)d_in[4];
    const float* a_val     = (const float*)d_in[5];
    const int*   b_row     = (const int*)d_in[6];
    const int*   b_col     = (const int*)d_in[7];
    const float* b_val     = (const float*)d_in[8];

    const int n_node  = in_sizes[0] / NFEAT;
    const int n_attri = in_sizes[1] / NFEAT;
    const int n       = n_node + n_attri;
    const int E1      = in_sizes[3];
    const int E2      = in_sizes[6];

    float* x1 = (float*)d_out;
    float* x2 = x1 + (size_t)n * NDIM;
    float* x3 = x2 + (size_t)n * NDIM;

    // Zero the scatter destinations (x2, x3). x1 is fully overwritten by GEMM.
    cudaMemsetAsync(x2, 0, (size_t)2 * n * NDIM * sizeof(float), 0);

    cudaFuncSetAttribute(gemm_kernel,
                         cudaFuncAttributeMaxDynamicSharedMemorySize,
                         GEMM_SMEM_BYTES);

    gemm_kernel<<<(n + TILE_ROWS - 1) / TILE_ROWS, 256, GEMM_SMEM_BYTES>>>(
        emb_node, emb_attri, n_node, n, W1, x1);

    // 256 threads = 8 warps, 4 edges per warp -> 32 edges per block.
    const int EPB = (256 / 32) * EDGES_PER_WARP;
    spmm_kernel<<<(E1 + EPB - 1) / EPB, 256>>>(a_row, a_col, a_val, x1, x2, E1);
    spmm_kernel<<<(E2 + EPB - 1) / EPB, 256>>>(b_row, b_col, b_val, x1, x3, E2);
}

// round 2
// speedup vs baseline: 1.6772x; 1.6772x over previous
#include <cuda_runtime.h>
#include <cuda_bf16.h>
#include <cstdint>

#define NFEAT 256
#define NDIM  128

// ---------------------------------------------------------------------------
// TF32 tensor-core GEMM: x1[r, j] = sum_k x0[r, k] * W1[j, k]
// Block tile: 64 (m) x 128 (n), K chunked by 32. 256 threads = 8 warps,
// warp tile 32x32 via mma.sync.m16n8k8 (2 m-iters x 4 n-iters).
// A and W staged in SMEM row-major [row][k] with stride 36 -> fragment loads
// hit banks (4*(t/4) + t%4) = t : conflict-free.
// Inputs converted to tf32 with cvt.rna (unbiased) once, at STS time.
// ---------------------------------------------------------------------------
#define BM 64
#define BK 32
#define LDA 36

__device__ __forceinline__ unsigned f2tf32(float x) {
    unsigned r;
    asm("cvt.rna.tf32.f32 %0, %1;" : "=r"(r) : "f"(x));
    return r;
}

__device__ __forceinline__ void mma_tf32(float c[4],
                                         const unsigned a[4],
                                         unsigned b0, unsigned b1) {
    asm volatile(
        "mma.sync.aligned.m16n8k8.row.col.f32.tf32.tf32.f32 "
        "{%0,%1,%2,%3}, {%4,%5,%6,%7}, {%8,%9}, {%0,%1,%2,%3};\n"
        : "+f"(c[0]), "+f"(c[1]), "+f"(c[2]), "+f"(c[3])
        : "r"(a[0]), "r"(a[1]), "r"(a[2]), "r"(a[3]), "r"(b0), "r"(b1));
}

__global__ void __launch_bounds__(256)
gemm_tf32_kernel(const float* __restrict__ emb_node,
                 const float* __restrict__ emb_attri,
                 int n_node, int n_total,
                 const float* __restrict__ W1,
                 float* __restrict__ x1)
{
    __shared__ unsigned As[BM * LDA];     // x0 chunk  [64][32] stride 36
    __shared__ unsigned Ws[NDIM * LDA];   // W1 chunk [128][32] stride 36

    const int tid  = threadIdx.x;
    const int lane = tid & 31;
    const int warp = tid >> 5;
    const int gid  = lane >> 2;   // 0..7
    const int tig  = lane & 3;    // 0..3
    const int wm   = warp & 1;    // 2 m-tiles of 32
    const int wn   = warp >> 1;   // 4 n-tiles of 32
    const int row0 = blockIdx.x * BM;

    float4 ra[2];   // staging regs: x0 (64*32 / 256 thr = 2 float4)
    float4 rw[4];   // staging regs: W1 (128*32 / 256 thr = 4 float4)

    auto ldg_chunk = [&](int k0) {
        #pragma unroll
        for (int i = 0; i < 2; i++) {
            int f = tid + 256 * i, r = f >> 3, u = f & 7;
            int grow = row0 + r;
            if (grow < n_total) {
                const float* src = (grow < n_node)
                    ? (emb_node  + (size_t)grow * NFEAT)
                    : (emb_attri + (size_t)(grow - n_node) * NFEAT);
                ra[i] = ((const float4*)(src + k0))[u];
            } else {
                ra[i] = make_float4(0.f, 0.f, 0.f, 0.f);
            }
        }
        #pragma unroll
        for (int i = 0; i < 4; i++) {
            int f = tid + 256 * i, r = f >> 3, u = f & 7;
            rw[i] = ((const float4*)(W1 + (size_t)r * NFEAT + k0))[u];
        }
    };

    auto sts_chunk = [&]() {
        #pragma unroll
        for (int i = 0; i < 2; i++) {
            int f = tid + 256 * i, r = f >> 3, u = f & 7;
            uint4 v = make_uint4(f2tf32(ra[i].x), f2tf32(ra[i].y),
                                 f2tf32(ra[i].z), f2tf32(ra[i].w));
            *(uint4*)&As[r * LDA + 4 * u] = v;
        }
        #pragma unroll
        for (int i = 0; i < 4; i++) {
            int f = tid + 256 * i, r = f >> 3, u = f & 7;
            uint4 v = make_uint4(f2tf32(rw[i].x), f2tf32(rw[i].y),
                                 f2tf32(rw[i].z), f2tf32(rw[i].w));
            *(uint4*)&Ws[r * LDA + 4 * u] = v;
        }
    };

    float c[2][4][4];
    #pragma unroll
    for (int mi = 0; mi < 2; mi++)
        #pragma unroll
        for (int ni = 0; ni < 4; ni++)
            #pragma unroll
            for (int q = 0; q < 4; q++) c[mi][ni][q] = 0.f;

    ldg_chunk(0);

    for (int ch = 0; ch < NFEAT / BK; ch++) {
        sts_chunk();
        __syncthreads();
        if (ch < NFEAT / BK - 1) ldg_chunk((ch + 1) * BK);

        #pragma unroll
        for (int s = 0; s < BK / 8; s++) {
            const int ks = s * 8;
            unsigned a[2][4];
            #pragma unroll
            for (int mi = 0; mi < 2; mi++) {
                int m = wm * 32 + mi * 16 + gid;
                a[mi][0] = As[m * LDA + ks + tig];
                a[mi][1] = As[(m + 8) * LDA + ks + tig];
                a[mi][2] = As[m * LDA + ks + tig + 4];
                a[mi][3] = As[(m + 8) * LDA + ks + tig + 4];
            }
            #pragma unroll
            for (int ni = 0; ni < 4; ni++) {
                int j = wn * 32 + ni * 8 + gid;
                unsigned b0 = Ws[j * LDA + ks + tig];
                unsigned b1 = Ws[j * LDA + ks + tig + 4];
                #pragma unroll
                for (int mi = 0; mi < 2; mi++)
                    mma_tf32(c[mi][ni], a[mi], b0, b1);
            }
        }
        __syncthreads();
    }

    // Epilogue: c0,c1 -> (row, 2*tig), (row, 2*tig+1); c2,c3 -> row+8.
    #pragma unroll
    for (int mi = 0; mi < 2; mi++) {
        int r0 = row0 + wm * 32 + mi * 16 + gid;
        #pragma unroll
        for (int ni = 0; ni < 4; ni++) {
            int j = wn * 32 + ni * 8 + 2 * tig;
            if (r0 < n_total)
                *(float2*)(x1 + (size_t)r0 * NDIM + j) =
                    make_float2(c[mi][ni][0], c[mi][ni][1]);
            if (r0 + 8 < n_total)
                *(float2*)(x1 + (size_t)(r0 + 8) * NDIM + j) =
                    make_float2(c[mi][ni][2], c[mi][ni][3]);
        }
    }
}

// ---------------------------------------------------------------------------
// SpMM scatter: out[row[e], :] += val[e] * x1[col[e], :]
// One warp handles 4 edges; each lane owns one float4 (gather + red.v4).
// x1 (52 MB) is L2-resident; this kernel runs at the LTS roofline.
// ---------------------------------------------------------------------------
#define EDGES_PER_WARP 4

__global__ void __launch_bounds__(256)
spmm_kernel(const int*   __restrict__ rows,
            const int*   __restrict__ cols,
            const float* __restrict__ vals,
            const float* __restrict__ x1,
            float*       __restrict__ out,
            int nedges)
{
    const int lane = threadIdx.x & 31;
    const int warp = blockIdx.x * (blockDim.x >> 5) + (threadIdx.x >> 5);
    const int e0 = warp * EDGES_PER_WARP;

    int   r[EDGES_PER_WARP];
    int   c[EDGES_PER_WARP];
    float v[EDGES_PER_WARP];

    #pragma unroll
    for (int i = 0; i < EDGES_PER_WARP; i++) {
        int e = e0 + i;
        if (e < nedges) { r[i] = rows[e]; c[i] = cols[e]; v[i] = vals[e]; }
        else            { r[i] = -1; c[i] = 0; v[i] = 0.f; }
    }

    float4 x[EDGES_PER_WARP];
    #pragma unroll
    for (int i = 0; i < EDGES_PER_WARP; i++) {
        if (r[i] >= 0)
            x[i] = ((const float4*)(x1 + (size_t)c[i] * NDIM))[lane];
    }

    #pragma unroll
    for (int i = 0; i < EDGES_PER_WARP; i++) {
        if (r[i] >= 0) {
            float* dst = out + (size_t)r[i] * NDIM + lane * 4;
            float a  = x[i].x * v[i];
            float b  = x[i].y * v[i];
            float cc = x[i].z * v[i];
            float d  = x[i].w * v[i];
            asm volatile("red.global.add.v4.f32 [%0], {%1, %2, %3, %4};"
                         :: "l"(dst), "f"(a), "f"(b), "f"(cc), "f"(d)
                         : "memory");
        }
    }
}

// ---------------------------------------------------------------------------
// kernel_launch
// ---------------------------------------------------------------------------
extern "C" void kernel_launch(void* const* d_in, const int* in_sizes, int n_in,
                              void* d_out, int out_size)
{
    const float* emb_node  = (const float*)d_in[0];
    const float* emb_attri = (const float*)d_in[1];
    const float* W1        = (const float*)d_in[2];
    const int*   a_row     = (const int*)d_in[3];
    const int*   a_col     = (const int*)d_in[4];
    const float* a_val     = (const float*)d_in[5];
    const int*   b_row     = (const int*)d_in[6];
    const int*   b_col     = (const int*)d_in[7];
    const float* b_val     = (const float*)d_in[8];

    const int n_node  = in_sizes[0] / NFEAT;
    const int n_attri = in_sizes[1] / NFEAT;
    const int n       = n_node + n_attri;
    const int E1      = in_sizes[3];
    const int E2      = in_sizes[6];

    float* x1 = (float*)d_out;
    float* x2 = x1 + (size_t)n * NDIM;
    float* x3 = x2 + (size_t)n * NDIM;

    // Zero scatter destinations (x2, x3); x1 fully overwritten by GEMM.
    cudaMemsetAsync(x2, 0, (size_t)2 * n * NDIM * sizeof(float), 0);

    gemm_tf32_kernel<<<(n + BM - 1) / BM, 256>>>(
        emb_node, emb_attri, n_node, n, W1, x1);

    const int EPB = (256 / 32) * EDGES_PER_WARP;   // 32 edges per block
    spmm_kernel<<<(E1 + EPB - 1) / EPB, 256>>>(a_row, a_col, a_val, x1, x2, E1);
    spmm_kernel<<<(E2 + EPB - 1) / EPB, 256>>>(b_row, b_col, b_val, x1, x3, E2);
}